// round 8
// baseline (speedup 1.0000x reference)
#include <cuda_runtime.h>

#define NMAX 50000
#define EMAX 800000
#define CAP  64           // bucket capacity per node (Binomial mean 16)
#define FULL 0xffffffffu

// ---------------- scratch (device globals) ----------------------------------
__device__ float d_buf0[NMAX * 64];
__device__ float d_buf1[NMAX * 64];
__device__ float d_acc [NMAX * 64];
__device__ float d_g   [NMAX * 64];
__device__ float d_hid [NMAX * 64];
__device__ float d_g2  [NMAX * 32];
__device__ float d_p   [NMAX];
__device__ float d_q   [NMAX];
__device__ float d_p2  [NMAX];
__device__ float d_q2  [NMAX];
__device__ int   d_cursor[NMAX];        // after fill: degree of each node
__device__ int   d_col [NMAX * CAP];    // bucketed adjacency (by dst)

// ---------------- bucket build -------------------------------------------------
__global__ void k_zero(int n) {
    int i = blockIdx.x * blockDim.x + threadIdx.x;
    if (i < n) d_cursor[i] = 0;
}

__global__ void k_fill(const int* __restrict__ src, const int* __restrict__ dst, int e) {
    for (int i = blockIdx.x * blockDim.x + threadIdx.x; i < e;
         i += gridDim.x * blockDim.x) {
        int dd  = dst[i];
        int pos = atomicAdd(&d_cursor[dd], 1);
        if (pos < CAP) d_col[dd * CAP + pos] = src[i];
    }
}

// ---------------- smoothing pass ------------------------------------------------
// Two select-based batches of 8 in-flight float4 gathers; warp-uniform branch
// for the second batch; serial tail only past 32 edges (~0.1% of nodes).
// MODE 1: acc = x + mean, write hout
// MODE 2: acc += mean, write hout
// MODE 4: acc += mean, no hout; fused p/q for conv1 (xs = acc*0.25)
template <int MODE>
__global__ void __launch_bounds__(256, 4)
k_pass(const float* __restrict__ hin, float* __restrict__ hout,
       const float* __restrict__ Watt, int n) {
    int w    = (blockIdx.x * blockDim.x + threadIdx.x) >> 5;
    int lane = threadIdx.x & 31;
    if (w >= n) return;
    int deg  = min(d_cursor[w], CAP);
    int base = w * CAP;
    const float4* __restrict__ h4 = (const float4*)hin;
    int half = lane >> 4, sub = lane & 15;
    float4 a = make_float4(0.f, 0.f, 0.f, 0.f);

    {   // batch 0: edges 0..15
        int   idx[8]; float wt[8]; float4 v[8];
#pragma unroll
        for (int i = 0; i < 8; i++) {
            int e = 2 * i + half;
            bool valid = e < deg;
            idx[i] = valid ? __ldg(&d_col[base + e]) : 0;
            wt [i] = valid ? 1.f : 0.f;
        }
#pragma unroll
        for (int i = 0; i < 8; i++) v[i] = h4[idx[i] * 16 + sub];
#pragma unroll
        for (int i = 0; i < 8; i++) {
            a.x += wt[i] * v[i].x; a.y += wt[i] * v[i].y;
            a.z += wt[i] * v[i].z; a.w += wt[i] * v[i].w;
        }
    }
    if (deg > 16) {   // warp-uniform: batch 1: edges 16..31
        int   idx[8]; float wt[8]; float4 v[8];
#pragma unroll
        for (int i = 0; i < 8; i++) {
            int e = 16 + 2 * i + half;
            bool valid = e < deg;
            idx[i] = valid ? __ldg(&d_col[base + e]) : 0;
            wt [i] = valid ? 1.f : 0.f;
        }
#pragma unroll
        for (int i = 0; i < 8; i++) v[i] = h4[idx[i] * 16 + sub];
#pragma unroll
        for (int i = 0; i < 8; i++) {
            a.x += wt[i] * v[i].x; a.y += wt[i] * v[i].y;
            a.z += wt[i] * v[i].z; a.w += wt[i] * v[i].w;
        }
        for (int e = 32 + half; e < deg; e += 2) {   // rare tail
            int s = __ldg(&d_col[base + e]);
            float4 v2 = h4[s * 16 + sub];
            a.x += v2.x; a.y += v2.y; a.z += v2.z; a.w += v2.w;
        }
    }

    a.x += __shfl_xor_sync(FULL, a.x, 16);
    a.y += __shfl_xor_sync(FULL, a.y, 16);
    a.z += __shfl_xor_sync(FULL, a.z, 16);
    a.w += __shfl_xor_sync(FULL, a.w, 16);
    float inv = 1.0f / (float)(deg > 1 ? deg : 1);
    a.x *= inv; a.y *= inv; a.z *= inv; a.w *= inv;

    if (half == 0) {
        if (MODE == 1 || MODE == 2) ((float4*)hout)[w * 16 + sub] = a;
        float4* acc4 = (float4*)d_acc;
        float4 t = (MODE == 1) ? h4[w * 16 + sub] : acc4[w * 16 + sub];
        t.x += a.x; t.y += a.y; t.z += a.z; t.w += a.w;
        acc4[w * 16 + sub] = t;
        if (MODE == 4) {
            float4 xs = make_float4(t.x * 0.25f, t.y * 0.25f, t.z * 0.25f, t.w * 0.25f);
            const float4* __restrict__ W4 = (const float4*)Watt;
            float4 wp = W4[sub], wq = W4[16 + sub];
            float pp = xs.x * wp.x + xs.y * wp.y + xs.z * wp.z + xs.w * wp.w;
            float qq = xs.x * wq.x + xs.y * wq.y + xs.z * wq.z + xs.w * wq.w;
#pragma unroll
            for (int off = 8; off; off >>= 1) {
                pp += __shfl_xor_sync(0x0000ffffu, pp, off);
                qq += __shfl_xor_sync(0x0000ffffu, qq, off);
            }
            if (sub == 0) { d_p[w] = pp; d_q[w] = qq; }
        }
    }
}

// ---------------- node GEMM: out[n,M] = (hin[n,64]*scale) @ W[64,M] ----------
template <int M>
__global__ void k_gemm(const float* __restrict__ hin, float scale,
                       const float* __restrict__ W, float* __restrict__ out, int n) {
    constexpr int NPG = 128 / M;
    __shared__ float Wsh[64 * M];
    __shared__ float xr[NPG][64];
    int o  = threadIdx.x % M;
    int ln = threadIdx.x / M;
    for (int idx = threadIdx.x; idx < 64 * M; idx += 128) Wsh[idx] = W[idx];
    __syncthreads();
    for (int base = blockIdx.x * NPG; base < n; base += gridDim.x * NPG) {
        int node = base + ln;
        if (node < n)
            for (int k = o; k < 64; k += M) xr[ln][k] = hin[node * 64 + k] * scale;
        __syncthreads();
        if (node < n) {
            float acc = 0.f;
#pragma unroll
            for (int k = 0; k < 64; k++) acc += xr[ln][k] * Wsh[k * M + o];
            out[node * M + o] = acc;
        }
        __syncthreads();
    }
}

// ---------------- conv1 edge aggregation (64-wide, relu, fused p2/q2) --------
__global__ void __launch_bounds__(256, 4)
k_edge64(const float* __restrict__ g,
         const float* __restrict__ p, const float* __restrict__ q,
         const float* __restrict__ batt,
         const float* __restrict__ Watt2,
         float* __restrict__ hid,
         float* __restrict__ pout, float* __restrict__ qout, int n) {
    int w    = (blockIdx.x * blockDim.x + threadIdx.x) >> 5;
    int lane = threadIdx.x & 31;
    if (w >= n) return;
    float qi = q[w] + batt[0];
    int deg  = min(d_cursor[w], CAP);
    int base = w * CAP;
    const float4* __restrict__ g4 = (const float4*)g;
    int half = lane >> 4, sub = lane & 15;
    float4 a = make_float4(0.f, 0.f, 0.f, 0.f);

    {   // batch 0: edges 0..15
        int idx[8]; float sc[8]; float4 v[8];
#pragma unroll
        for (int i = 0; i < 8; i++) {
            int e = 2 * i + half;
            bool valid = e < deg;
            idx[i] = valid ? __ldg(&d_col[base + e]) : 0;
            float t = p[idx[i]] + qi;
            t = t > 0.f ? t : 0.01f * t;     // leaky_relu
            sc[i] = valid ? t : 0.f;
        }
#pragma unroll
        for (int i = 0; i < 8; i++) v[i] = g4[idx[i] * 16 + sub];
#pragma unroll
        for (int i = 0; i < 8; i++) {
            a.x += sc[i] * v[i].x; a.y += sc[i] * v[i].y;
            a.z += sc[i] * v[i].z; a.w += sc[i] * v[i].w;
        }
    }
    if (deg > 16) {   // batch 1: edges 16..31
        int idx[8]; float sc[8]; float4 v[8];
#pragma unroll
        for (int i = 0; i < 8; i++) {
            int e = 16 + 2 * i + half;
            bool valid = e < deg;
            idx[i] = valid ? __ldg(&d_col[base + e]) : 0;
            float t = p[idx[i]] + qi;
            t = t > 0.f ? t : 0.01f * t;
            sc[i] = valid ? t : 0.f;
        }
#pragma unroll
        for (int i = 0; i < 8; i++) v[i] = g4[idx[i] * 16 + sub];
#pragma unroll
        for (int i = 0; i < 8; i++) {
            a.x += sc[i] * v[i].x; a.y += sc[i] * v[i].y;
            a.z += sc[i] * v[i].z; a.w += sc[i] * v[i].w;
        }
        for (int e = 32 + half; e < deg; e += 2) {
            int s = __ldg(&d_col[base + e]);
            float t = p[s] + qi;
            float sc2 = t > 0.f ? t : 0.01f * t;
            float4 v2 = g4[s * 16 + sub];
            a.x += sc2 * v2.x; a.y += sc2 * v2.y; a.z += sc2 * v2.z; a.w += sc2 * v2.w;
        }
    }

    a.x += __shfl_xor_sync(FULL, a.x, 16);
    a.y += __shfl_xor_sync(FULL, a.y, 16);
    a.z += __shfl_xor_sync(FULL, a.z, 16);
    a.w += __shfl_xor_sync(FULL, a.w, 16);
    a.x = fmaxf(a.x, 0.f); a.y = fmaxf(a.y, 0.f);
    a.z = fmaxf(a.z, 0.f); a.w = fmaxf(a.w, 0.f);
    if (half == 0) ((float4*)hid)[w * 16 + sub] = a;
    // fused p2/q2: lanes 0-15 -> p (Watt2[:64]), lanes 16-31 -> q (Watt2[64:])
    const float4* __restrict__ W4 = (const float4*)Watt2;
    float4 ww = W4[lane];
    float d = a.x * ww.x + a.y * ww.y + a.z * ww.z + a.w * ww.w;
#pragma unroll
    for (int off = 8; off; off >>= 1) d += __shfl_xor_sync(FULL, d, off);
    if (lane == 0)  pout[w] = d;
    if (lane == 16) qout[w] = d;
}

// ---------------- conv2 edge aggregation (32-wide, full 32-edge batch) -------
__global__ void __launch_bounds__(256, 4)
k_edge32(const float* __restrict__ g2,
         const float* __restrict__ p, const float* __restrict__ q,
         const float* __restrict__ batt,
         float* __restrict__ out, int n) {
    int w    = (blockIdx.x * blockDim.x + threadIdx.x) >> 5;
    int lane = threadIdx.x & 31;
    if (w >= n) return;
    float qi = q[w] + batt[0];
    int deg  = min(d_cursor[w], CAP);
    int base = w * CAP;
    const float4* __restrict__ g4 = (const float4*)g2;
    int quad = lane >> 3, sub = lane & 7;
    float4 a = make_float4(0.f, 0.f, 0.f, 0.f);

    {   // 32 edges, 8 per lane-group, one batch
        int idx[8]; float sc[8]; float4 v[8];
#pragma unroll
        for (int i = 0; i < 8; i++) {
            int e = 4 * i + quad;
            bool valid = e < deg;
            idx[i] = valid ? __ldg(&d_col[base + e]) : 0;
            float t = p[idx[i]] + qi;
            t = t > 0.f ? t : 0.01f * t;
            sc[i] = valid ? t : 0.f;
        }
#pragma unroll
        for (int i = 0; i < 8; i++) v[i] = g4[idx[i] * 8 + sub];
#pragma unroll
        for (int i = 0; i < 8; i++) {
            a.x += sc[i] * v[i].x; a.y += sc[i] * v[i].y;
            a.z += sc[i] * v[i].z; a.w += sc[i] * v[i].w;
        }
    }
    for (int e = 32 + quad; e < deg; e += 4) {   // essentially never
        int s = __ldg(&d_col[base + e]);
        float t = p[s] + qi;
        float sc = t > 0.f ? t : 0.01f * t;
        float4 v = g4[s * 8 + sub];
        a.x += sc * v.x; a.y += sc * v.y; a.z += sc * v.z; a.w += sc * v.w;
    }

    a.x += __shfl_xor_sync(FULL, a.x, 16);
    a.y += __shfl_xor_sync(FULL, a.y, 16);
    a.z += __shfl_xor_sync(FULL, a.z, 16);
    a.w += __shfl_xor_sync(FULL, a.w, 16);
    a.x += __shfl_xor_sync(FULL, a.x, 8);
    a.y += __shfl_xor_sync(FULL, a.y, 8);
    a.z += __shfl_xor_sync(FULL, a.z, 8);
    a.w += __shfl_xor_sync(FULL, a.w, 8);
    if (lane < 8) ((float4*)out)[w * 8 + sub] = a;
}

// ---------------- launch ------------------------------------------------------
extern "C" void kernel_launch(void* const* d_in, const int* in_sizes, int n_in,
                              void* d_out, int out_size) {
    const float* x     = (const float*)d_in[0];
    const int*   ei    = (const int*)  d_in[1];
    const float* Watt1 = (const float*)d_in[2];
    const float* batt1 = (const float*)d_in[3];
    const float* Wlin1 = (const float*)d_in[4];
    const float* Watt2 = (const float*)d_in[5];
    const float* batt2 = (const float*)d_in[6];
    const float* Wlin2 = (const float*)d_in[7];

    int n = in_sizes[0] / 64;   // 50000
    int e = in_sizes[1] / 2;    // 800000
    const int* src = ei;
    const int* dst = ei + e;

    float *buf0, *buf1, *accp, *gp, *hidp, *g2p, *pp, *qp, *p2p, *q2p;
    cudaGetSymbolAddress((void**)&buf0, d_buf0);
    cudaGetSymbolAddress((void**)&buf1, d_buf1);
    cudaGetSymbolAddress((void**)&accp, d_acc);
    cudaGetSymbolAddress((void**)&gp,   d_g);
    cudaGetSymbolAddress((void**)&hidp, d_hid);
    cudaGetSymbolAddress((void**)&g2p,  d_g2);
    cudaGetSymbolAddress((void**)&pp,   d_p);
    cudaGetSymbolAddress((void**)&qp,   d_q);
    cudaGetSymbolAddress((void**)&p2p,  d_p2);
    cudaGetSymbolAddress((void**)&q2p,  d_q2);

    const int TB = 256;
    int wb = (n * 32 + TB - 1) / TB;

    // bucket build
    k_zero<<<(n + TB - 1) / TB, TB>>>(n);
    k_fill<<<592, TB>>>(src, dst, e);

    // graphSmoothing (pass3 fuses conv1 p/q with the 0.25 scale)
    k_pass<1><<<wb, TB>>>(x,    buf0, Watt1, n);
    k_pass<2><<<wb, TB>>>(buf0, buf1, Watt1, n);   // <- 4th launch: profiled
    k_pass<4><<<wb, TB>>>(buf1, buf0, Watt1, n);

    // conv1
    k_gemm<64><<<592, 128>>>(accp, 0.25f, Wlin1, gp, n);
    k_edge64<<<wb, TB>>>(gp, pp, qp, batt1, Watt2, hidp, p2p, q2p, n);

    // conv2
    k_gemm<32><<<592, 128>>>(hidp, 1.0f, Wlin2, g2p, n);
    k_edge32<<<wb, TB>>>(g2p, p2p, q2p, batt2, (float*)d_out, n);
}

// round 9
// speedup vs baseline: 1.2787x; 1.2787x over previous
#include <cuda_runtime.h>

#define NMAX 50000
#define EMAX 800000
#define CAP  64           // bucket capacity per node (Binomial mean 16)
#define FULL 0xffffffffu

// ---------------- scratch (device globals; zero-initialized at load) ---------
__device__ float d_buf0[NMAX * 64];
__device__ float d_buf1[NMAX * 64];
__device__ float d_acc [NMAX * 64];
__device__ float d_g2  [NMAX * 32];
__device__ float d_p   [NMAX];
__device__ float d_q   [NMAX];
__device__ float d_p2  [NMAX];
__device__ float d_q2  [NMAX];
__device__ int   d_cursor[NMAX];        // zeroed by k_edge32 at end of each launch
__device__ int   d_col [NMAX * CAP];    // bucketed adjacency (by dst)

// ---------------- bucket fill (cursor pre-zeroed by previous launch) ---------
__global__ void k_fill(const int* __restrict__ src, const int* __restrict__ dst, int e) {
    for (int i = blockIdx.x * blockDim.x + threadIdx.x; i < e;
         i += gridDim.x * blockDim.x) {
        int dd  = dst[i];
        int pos = atomicAdd(&d_cursor[dd], 1);
        if (pos < CAP) d_col[dd * CAP + pos] = src[i];
    }
}

// ---------------- smoothing pass (R6 form: flat predicated pair-gather) ------
// MODE 1: acc = x + mean, write hout
// MODE 2: acc += mean, write hout
// MODE 4: acc += mean, no hout; fused p/q for conv1 (xs = acc*0.25)
template <int MODE>
__global__ void k_pass(const float* __restrict__ hin, float* __restrict__ hout,
                       const float* __restrict__ Watt, int n) {
    int w    = (blockIdx.x * blockDim.x + threadIdx.x) >> 5;
    int lane = threadIdx.x & 31;
    if (w >= n) return;
    int deg  = min(d_cursor[w], CAP);
    int base = w * CAP;
    const float4* __restrict__ h4 = (const float4*)hin;
    int half = lane >> 4, sub = lane & 15;
    float4 a = make_float4(0.f, 0.f, 0.f, 0.f);

#pragma unroll
    for (int e = 0; e < 32; e += 2) {
        if (e + half < deg) {
            int s = __ldg(&d_col[base + e + half]);
            float4 v = h4[s * 16 + sub];
            a.x += v.x; a.y += v.y; a.z += v.z; a.w += v.w;
        }
    }
    for (int e = 32; e < deg; e += 2) {               // rare tail (deg>32)
        if (e + half < deg) {
            int s = __ldg(&d_col[base + e + half]);
            float4 v = h4[s * 16 + sub];
            a.x += v.x; a.y += v.y; a.z += v.z; a.w += v.w;
        }
    }

    a.x += __shfl_xor_sync(FULL, a.x, 16);
    a.y += __shfl_xor_sync(FULL, a.y, 16);
    a.z += __shfl_xor_sync(FULL, a.z, 16);
    a.w += __shfl_xor_sync(FULL, a.w, 16);
    float inv = 1.0f / (float)(deg > 1 ? deg : 1);
    a.x *= inv; a.y *= inv; a.z *= inv; a.w *= inv;

    if (half == 0) {
        if (MODE == 1 || MODE == 2) ((float4*)hout)[w * 16 + sub] = a;
        float4* acc4 = (float4*)d_acc;
        float4 t = (MODE == 1) ? h4[w * 16 + sub] : acc4[w * 16 + sub];
        t.x += a.x; t.y += a.y; t.z += a.z; t.w += a.w;
        acc4[w * 16 + sub] = t;
        if (MODE == 4) {
            float4 xs = make_float4(t.x * 0.25f, t.y * 0.25f, t.z * 0.25f, t.w * 0.25f);
            const float4* __restrict__ W4 = (const float4*)Watt;
            float4 wp = W4[sub], wq = W4[16 + sub];
            float pp = xs.x * wp.x + xs.y * wp.y + xs.z * wp.z + xs.w * wp.w;
            float qq = xs.x * wq.x + xs.y * wq.y + xs.z * wq.z + xs.w * wq.w;
#pragma unroll
            for (int off = 8; off; off >>= 1) {
                pp += __shfl_xor_sync(0x0000ffffu, pp, off);
                qq += __shfl_xor_sync(0x0000ffffu, qq, off);
            }
            if (sub == 0) { d_p[w] = pp; d_q[w] = qq; }
        }
    }
}

// ---------------- conv1 fused: gather(acc) -> GEMV W1 -> relu -> p2/q2 + GEMV W2
// Linearity: sum_e sc_e*(xs_s@W1) = (0.25*sum_e sc_e*acc_s)@W1.
// Persistent-ish blocks: weights loaded to shared once per block, nodes grid-strided.
__global__ void k_conv1(const float* __restrict__ acc,
                        const float* __restrict__ p, const float* __restrict__ q,
                        const float* __restrict__ batt1,
                        const float* __restrict__ Wlin1,
                        const float* __restrict__ Watt2,
                        const float* __restrict__ Wlin2,
                        float* __restrict__ g2out,
                        float* __restrict__ pout, float* __restrict__ qout, int n) {
    __shared__ float W1sh[64 * 64];   // [k][o] row-major, 16KB
    __shared__ float W2sh[64 * 32];   // 8KB
    __shared__ float Wash[128];
    __shared__ float ush[8][64];      // per-warp staging

    for (int i = threadIdx.x; i < 64 * 64; i += blockDim.x) W1sh[i] = Wlin1[i];
    for (int i = threadIdx.x; i < 64 * 32; i += blockDim.x) W2sh[i] = Wlin2[i];
    if (threadIdx.x < 128) Wash[threadIdx.x] = Watt2[threadIdx.x];
    __syncthreads();

    int wid  = threadIdx.x >> 5;
    int lane = threadIdx.x & 31;
    int half = lane >> 4, sub = lane & 15;
    float b1 = batt1[0];
    const float4* __restrict__ a4 = (const float4*)acc;

    for (int w = blockIdx.x * 8 + wid; w < n; w += gridDim.x * 8) {
        float qi = q[w] + b1;
        int deg  = min(d_cursor[w], CAP);
        int base = w * CAP;
        float4 a = make_float4(0.f, 0.f, 0.f, 0.f);

#pragma unroll
        for (int e = 0; e < 32; e += 2) {
            if (e + half < deg) {
                int s = __ldg(&d_col[base + e + half]);
                float t = p[s] + qi;
                float sc = t > 0.f ? t : 0.01f * t;   // leaky_relu
                float4 v = a4[s * 16 + sub];
                a.x += sc * v.x; a.y += sc * v.y; a.z += sc * v.z; a.w += sc * v.w;
            }
        }
        for (int e = 32; e < deg; e += 2) {
            if (e + half < deg) {
                int s = __ldg(&d_col[base + e + half]);
                float t = p[s] + qi;
                float sc = t > 0.f ? t : 0.01f * t;
                float4 v = a4[s * 16 + sub];
                a.x += sc * v.x; a.y += sc * v.y; a.z += sc * v.z; a.w += sc * v.w;
            }
        }
        a.x += __shfl_xor_sync(FULL, a.x, 16);
        a.y += __shfl_xor_sync(FULL, a.y, 16);
        a.z += __shfl_xor_sync(FULL, a.z, 16);
        a.w += __shfl_xor_sync(FULL, a.w, 16);

        // stage u (64 floats) in shared from the low half-warp
        if (half == 0) {
            ush[wid][sub * 4 + 0] = a.x;
            ush[wid][sub * 4 + 1] = a.y;
            ush[wid][sub * 4 + 2] = a.z;
            ush[wid][sub * 4 + 3] = a.w;
        }
        __syncwarp();

        // conv1 GEMV + relu: lane computes hid[lane], hid[lane+32]
        float h0 = 0.f, h1 = 0.f;
#pragma unroll 8
        for (int k = 0; k < 64; k++) {
            float uk = ush[wid][k];
            h0 += uk * W1sh[k * 64 + lane];
            h1 += uk * W1sh[k * 64 + lane + 32];
        }
        h0 = fmaxf(0.25f * h0, 0.f);
        h1 = fmaxf(0.25f * h1, 0.f);

        // p2/q2 = hid . Watt2[:64], hid . Watt2[64:]
        float pp = h0 * Wash[lane] + h1 * Wash[lane + 32];
        float qq = h0 * Wash[64 + lane] + h1 * Wash[96 + lane];
#pragma unroll
        for (int off = 16; off; off >>= 1) {
            pp += __shfl_xor_sync(FULL, pp, off);
            qq += __shfl_xor_sync(FULL, qq, off);
        }
        if (lane == 0) { pout[w] = pp; qout[w] = qq; }

        // restage hid for the 64x32 GEMV
        __syncwarp();
        ush[wid][lane]      = h0;
        ush[wid][lane + 32] = h1;
        __syncwarp();

        float g = 0.f;
#pragma unroll 8
        for (int k = 0; k < 64; k++) g += ush[wid][k] * W2sh[k * 32 + lane];
        g2out[w * 32 + lane] = g;
        __syncwarp();
    }
}

// ---------------- conv2 edge aggregation (R6 form) + cursor re-zero ----------
__global__ void k_edge32(const float* __restrict__ g2,
                         const float* __restrict__ p, const float* __restrict__ q,
                         const float* __restrict__ batt,
                         float* __restrict__ out, int n) {
    int w    = (blockIdx.x * blockDim.x + threadIdx.x) >> 5;
    int lane = threadIdx.x & 31;
    if (w >= n) return;
    float qi = q[w] + batt[0];
    int deg  = min(d_cursor[w], CAP);
    int base = w * CAP;
    const float4* __restrict__ g4 = (const float4*)g2;
    int quad = lane >> 3, sub = lane & 7;
    float4 a = make_float4(0.f, 0.f, 0.f, 0.f);

#pragma unroll
    for (int e = 0; e < 32; e += 4) {
        if (e + quad < deg) {
            int s = __ldg(&d_col[base + e + quad]);
            float t = p[s] + qi;
            float sc = t > 0.f ? t : 0.01f * t;
            float4 v = g4[s * 8 + sub];
            a.x += sc * v.x; a.y += sc * v.y; a.z += sc * v.z; a.w += sc * v.w;
        }
    }
    for (int e = 32; e < deg; e += 4) {
        if (e + quad < deg) {
            int s = __ldg(&d_col[base + e + quad]);
            float t = p[s] + qi;
            float sc = t > 0.f ? t : 0.01f * t;
            float4 v = g4[s * 8 + sub];
            a.x += sc * v.x; a.y += sc * v.y; a.z += sc * v.z; a.w += sc * v.w;
        }
    }

    a.x += __shfl_xor_sync(FULL, a.x, 16);
    a.y += __shfl_xor_sync(FULL, a.y, 16);
    a.z += __shfl_xor_sync(FULL, a.z, 16);
    a.w += __shfl_xor_sync(FULL, a.w, 16);
    a.x += __shfl_xor_sync(FULL, a.x, 8);
    a.y += __shfl_xor_sync(FULL, a.y, 8);
    a.z += __shfl_xor_sync(FULL, a.z, 8);
    a.w += __shfl_xor_sync(FULL, a.w, 8);
    if (lane < 8) ((float4*)out)[w * 8 + sub] = a;

    // leave cursor zeroed for the next launch's k_fill (deterministic state)
    if (lane == 0) d_cursor[w] = 0;
}

// ---------------- launch ------------------------------------------------------
extern "C" void kernel_launch(void* const* d_in, const int* in_sizes, int n_in,
                              void* d_out, int out_size) {
    const float* x     = (const float*)d_in[0];
    const int*   ei    = (const int*)  d_in[1];
    const float* Watt1 = (const float*)d_in[2];
    const float* batt1 = (const float*)d_in[3];
    const float* Wlin1 = (const float*)d_in[4];
    const float* Watt2 = (const float*)d_in[5];
    const float* batt2 = (const float*)d_in[6];
    const float* Wlin2 = (const float*)d_in[7];

    int n = in_sizes[0] / 64;   // 50000
    int e = in_sizes[1] / 2;    // 800000
    const int* src = ei;
    const int* dst = ei + e;

    float *buf0, *buf1, *accp, *g2p, *pp, *qp, *p2p, *q2p;
    cudaGetSymbolAddress((void**)&buf0, d_buf0);
    cudaGetSymbolAddress((void**)&buf1, d_buf1);
    cudaGetSymbolAddress((void**)&accp, d_acc);
    cudaGetSymbolAddress((void**)&g2p,  d_g2);
    cudaGetSymbolAddress((void**)&pp,   d_p);
    cudaGetSymbolAddress((void**)&qp,   d_q);
    cudaGetSymbolAddress((void**)&p2p,  d_p2);
    cudaGetSymbolAddress((void**)&q2p,  d_q2);

    const int TB = 256;
    int wb = (n * 32 + TB - 1) / TB;

    // bucket build (cursor zeroed by previous launch's k_edge32 / load-time init)
    k_fill<<<592, TB>>>(src, dst, e);

    // graphSmoothing (pass3 fuses conv1 p/q with the 0.25 scale)
    k_pass<1><<<wb, TB>>>(x,    buf0, Watt1, n);
    k_pass<2><<<wb, TB>>>(buf0, buf1, Watt1, n);
    k_pass<4><<<wb, TB>>>(buf1, buf0, Watt1, n);   // <- 4th launch: profiled

    // conv1 fused: gather(acc) -> GEMV W1 -> relu -> p2/q2 + GEMV W2 -> g2
    k_conv1<<<592, TB>>>(accp, pp, qp, batt1, Wlin1, Watt2, Wlin2,
                         g2p, p2p, q2p, n);

    // conv2 (final; re-zeroes d_cursor)
    k_edge32<<<wb, TB>>>(g2p, p2p, q2p, batt2, (float*)d_out, n);
}